// round 13
// baseline (speedup 1.0000x reference)
#include <cuda_runtime.h>
#include <cuda_fp16.h>
#include <cstdint>

#define N_NODES 50000
#define N_EDGES 1600000
#define F_IN    128
#define H_DIM   128
#define BN_EPS  1e-5f
#define CAP     128          // bucket capacity per node (Poisson λ=32: P(deg>128) ~ 1e-40)

// ---------------- scratch (no cudaMalloc allowed) ----------------
__device__ int    g_cnt[N_NODES];                 // in-degree (edges only)
__device__ float  g_dinv[N_NODES];
__device__ int    g_bkt[(size_t)N_NODES * CAP];   // bucketed CSR (sentinel-padded to x32)
// +1 zero row at index N_NODES for sentinel gathers
__device__ __half g_y1[(size_t)(N_NODES + 1) * H_DIM];  // bn0(x)@W1, prescaled by dinv
__device__ float  g_y2[(size_t)N_NODES * 2];            // dinv * (h2 @ W2)

// ---------------- one-pass bucket fill (2 edges / thread, proven) ----------------
__global__ void k_fill(const int* __restrict__ ei) {
    int t = blockIdx.x * blockDim.x + threadIdx.x;
    int e = t * 2;
    if (e < N_EDGES) {
        int2 sv = *(const int2*)(ei + e);
        int2 dv = *(const int2*)(ei + N_EDGES + e);
        int p0 = atomicAdd(&g_cnt[dv.x], 1);
        if (p0 < CAP) g_bkt[(size_t)dv.x * CAP + p0] = sv.x;
        int p1 = atomicAdd(&g_cnt[dv.y], 1);
        if (p1 < CAP) g_bkt[(size_t)dv.y * CAP + p1] = sv.y;
    }
}

// ---- prescale y1 by dinv, persist dinv, pad buckets to x32 with sentinel ----
// one warp per row (t>>5 == row, 32 threads handle 32 uint2 of the row)
__global__ void __launch_bounds__(256) k_scale() {
    int t = blockIdx.x * blockDim.x + threadIdx.x;
    if (t >= (N_NODES + 1) * 32) return;
    int row  = t >> 5;
    int lane = t & 31;
    uint2* Y = (uint2*)g_y1;
    if (row < N_NODES) {
        int cnt = g_cnt[row];
        float d = rsqrtf((float)(cnt + 1));   // +1 self loop
        if (lane == 0) g_dinv[row] = d;
        // pad bucket region [c, roundup32(c)) with sentinel (zero row)
        int c  = cnt < CAP ? cnt : CAP;
        int pe = (c + 31) & ~31;
        int p  = c + lane;
        if (p < pe) g_bkt[(size_t)row * CAP + p] = N_NODES;
        // scale
        uint2 u = Y[t];
        __half2 dv2 = __float2half2_rn(d);
        *(__half2*)&u.x = __hmul2(*(__half2*)&u.x, dv2);
        *(__half2*)&u.y = __hmul2(*(__half2*)&u.y, dv2);
        Y[t] = u;
    } else {
        Y[t] = make_uint2(0u, 0u);            // zero row for sentinels
    }
}

// ============== GEMM1: y1 = bn0(x) @ W1  (HMMA fp16, fp32 accum) ==============
__device__ __forceinline__ uint32_t smem_u32(const void* p) {
    return (uint32_t)__cvta_generic_to_shared(p);
}
__device__ __forceinline__ void ldm_x4(uint32_t& r0, uint32_t& r1, uint32_t& r2, uint32_t& r3,
                                       uint32_t a) {
    asm volatile("ldmatrix.sync.aligned.m8n8.x4.shared.b16 {%0,%1,%2,%3}, [%4];"
                 : "=r"(r0), "=r"(r1), "=r"(r2), "=r"(r3) : "r"(a));
}
__device__ __forceinline__ void ldm_x4_t(uint32_t& r0, uint32_t& r1, uint32_t& r2, uint32_t& r3,
                                         uint32_t a) {
    asm volatile("ldmatrix.sync.aligned.m8n8.x4.trans.shared.b16 {%0,%1,%2,%3}, [%4];"
                 : "=r"(r0), "=r"(r1), "=r"(r2), "=r"(r3) : "r"(a));
}
__device__ __forceinline__ void mma16816(float* c, uint32_t a0, uint32_t a1, uint32_t a2,
                                         uint32_t a3, uint32_t b0, uint32_t b1) {
    asm volatile("mma.sync.aligned.m16n8k16.row.col.f32.f16.f16.f32 "
                 "{%0,%1,%2,%3}, {%4,%5,%6,%7}, {%8,%9}, {%0,%1,%2,%3};"
                 : "+f"(c[0]), "+f"(c[1]), "+f"(c[2]), "+f"(c[3])
                 : "r"(a0), "r"(a1), "r"(a2), "r"(a3), "r"(b0), "r"(b1));
}

#define SW_STRIDE 136
#define SA_STRIDE 24

__global__ void __launch_bounds__(256) k_gemm1(
        const float* __restrict__ x,
        const float* __restrict__ g0, const float* __restrict__ b0,
        const float* __restrict__ m0, const float* __restrict__ v0,
        const float* __restrict__ W1) {
    __shared__ __half sW[128 * SW_STRIDE];
    __shared__ __half sA[128 * SA_STRIDE];
    __shared__ float  sa[128], sc[128];

    const int tid  = threadIdx.x;
    const int wid  = tid >> 5;
    const int lane = tid & 31;
    const int bm   = blockIdx.x * 128;

    if (tid < 128) {
        float a = g0[tid] * rsqrtf(v0[tid] + BN_EPS);
        sa[tid] = a;
        sc[tid] = b0[tid] - m0[tid] * a;
    }
    for (int i = tid; i < 128 * 128; i += 256) {
        int k = i >> 7, n = i & 127;
        sW[k * SW_STRIDE + n] = __float2half(W1[i]);
    }
    __syncthreads();

    const int m0r   = wid * 16;
    const uint32_t aAddr = smem_u32(&sA[(m0r + (lane & 15)) * SA_STRIDE + (lane >> 4) * 8]);
    const int bRow  = (lane & 7) + ((lane >> 4) & 1) * 8;
    const int bColO = ((lane >> 3) & 1) * 8;

    const int arow = tid >> 1;
    const int akk  = (tid & 1) * 8;
    const int grow = bm + arow;

    float acc[16][4];
#pragma unroll
    for (int t = 0; t < 16; t++)
#pragma unroll
        for (int j = 0; j < 4; j++) acc[t][j] = 0.f;

    for (int k0 = 0; k0 < F_IN; k0 += 16) {
        float4 xv0 = make_float4(0.f, 0.f, 0.f, 0.f), xv1 = xv0;
        if (grow < N_NODES) {
            xv0 = *(const float4*)(x + (size_t)grow * F_IN + k0 + akk);
            xv1 = *(const float4*)(x + (size_t)grow * F_IN + k0 + akk + 4);
        }
        __half* dst = &sA[arow * SA_STRIDE + akk];
        dst[0] = __float2half(xv0.x * sa[k0 + akk]     + sc[k0 + akk]);
        dst[1] = __float2half(xv0.y * sa[k0 + akk + 1] + sc[k0 + akk + 1]);
        dst[2] = __float2half(xv0.z * sa[k0 + akk + 2] + sc[k0 + akk + 2]);
        dst[3] = __float2half(xv0.w * sa[k0 + akk + 3] + sc[k0 + akk + 3]);
        dst[4] = __float2half(xv1.x * sa[k0 + akk + 4] + sc[k0 + akk + 4]);
        dst[5] = __float2half(xv1.y * sa[k0 + akk + 5] + sc[k0 + akk + 5]);
        dst[6] = __float2half(xv1.z * sa[k0 + akk + 6] + sc[k0 + akk + 6]);
        dst[7] = __float2half(xv1.w * sa[k0 + akk + 7] + sc[k0 + akk + 7]);
        __syncthreads();

        uint32_t a0, a1, a2, a3;
        ldm_x4(a0, a1, a2, a3, aAddr);
#pragma unroll
        for (int np = 0; np < 8; np++) {
            uint32_t r0, r1, r2, r3;
            uint32_t bAddr = smem_u32(&sW[(k0 + bRow) * SW_STRIDE + np * 16 + bColO]);
            ldm_x4_t(r0, r1, r2, r3, bAddr);
            mma16816(acc[np * 2],     a0, a1, a2, a3, r0, r2);
            mma16816(acc[np * 2 + 1], a0, a1, a2, a3, r1, r3);
        }
        __syncthreads();
    }

    int r0g = bm + m0r + (lane >> 2);
    int r1g = r0g + 8;
    int ncol = (lane & 3) * 2;
#pragma unroll
    for (int t = 0; t < 16; t++) {
        int n = t * 8 + ncol;
        if (r0g < N_NODES) {
            __half2 h = __floats2half2_rn(acc[t][0], acc[t][1]);
            *(__half2*)(g_y1 + (size_t)r0g * H_DIM + n) = h;
        }
        if (r1g < N_NODES) {
            __half2 h = __floats2half2_rn(acc[t][2], acc[t][3]);
            *(__half2*)(g_y1 + (size_t)r1g * H_DIM + n) = h;
        }
    }
}

// ========= agg1 + bn1 + relu + GEMM2 fused (warp per node) =========
// Sentinel-padded buckets -> branchless loop; __ldcg L2-direct gathers.
__global__ void __launch_bounds__(256) k_agg1(
        const float* __restrict__ g1, const float* __restrict__ be1,
        const float* __restrict__ m1, const float* __restrict__ v1,
        const float* __restrict__ b1, const float* __restrict__ W2) {
    int w = (blockIdx.x * blockDim.x + threadIdx.x) >> 5;
    int lane = threadIdx.x & 31;
    if (w >= N_NODES) return;

    const uint2* __restrict__ Y = (const uint2*)g_y1;   // 32 uint2 per row (prescaled)
    const int* __restrict__ bkt = g_bkt + (size_t)w * CAP;
    int cnt  = g_cnt[w];
    int c    = cnt < CAP ? cnt : CAP;
    float dw = g_dinv[w];

    // self loop: prescaled own row, fp32
    float2 acc0, acc1;
    {
        uint2 u = Y[(size_t)w * 32 + lane];
        acc0 = __half22float2(*(__half2*)&u.x);
        acc1 = __half22float2(*(__half2*)&u.y);
    }

    const __half2 hz = __float2half2_rn(0.f);
    int ngt = (c + 7) >> 3;                    // groups of 8 (padded -> safe)
    for (int b0 = 0; b0 < ngt; b0 += 4) {
        int sl = bkt[(b0 << 3) + lane];        // unconditional: padded to x32
        int ge = ngt - b0; if (ge > 4) ge = 4;
        for (int g = 0; g < ge; g++) {
            __half2 a0 = hz, a1 = hz;
#pragma unroll
            for (int j = 0; j < 8; j++) {
                int s = __shfl_sync(0xffffffffu, sl, (g << 3) + j);
                uint2 u = __ldcg(Y + (size_t)s * 32 + lane);
                a0 = __hadd2(a0, *(__half2*)&u.x);
                a1 = __hadd2(a1, *(__half2*)&u.y);
            }
            float2 f0 = __half22float2(a0);
            float2 f1 = __half22float2(a1);
            acc0.x += f0.x; acc0.y += f0.y;
            acc1.x += f1.x; acc1.y += f1.y;
        }
    }

    // bn1 + relu
    int f = lane * 4;
    float4 ga = *(const float4*)(g1 + f);
    float4 va = *(const float4*)(v1 + f);
    float4 ba = *(const float4*)(be1 + f);
    float4 ma = *(const float4*)(m1 + f);
    float4 bb = *(const float4*)(b1 + f);

    float h[4];
    {
        float a = ga.x * rsqrtf(va.x + BN_EPS);
        h[0] = fmaxf(a * (dw * acc0.x + bb.x) + (ba.x - ma.x * a), 0.f);
        a = ga.y * rsqrtf(va.y + BN_EPS);
        h[1] = fmaxf(a * (dw * acc0.y + bb.y) + (ba.y - ma.y * a), 0.f);
        a = ga.z * rsqrtf(va.z + BN_EPS);
        h[2] = fmaxf(a * (dw * acc1.x + bb.z) + (ba.z - ma.z * a), 0.f);
        a = ga.w * rsqrtf(va.w + BN_EPS);
        h[3] = fmaxf(a * (dw * acc1.y + bb.w) + (ba.w - ma.w * a), 0.f);
    }

    // fused GEMM2: y2[w] = dinv[w] * (h2[w] @ W2)
    float4 wa = *(const float4*)(W2 + f * 2);
    float4 wb = *(const float4*)(W2 + f * 2 + 4);
    float d0 = h[0] * wa.x + h[1] * wa.z + h[2] * wb.x + h[3] * wb.z;
    float d1 = h[0] * wa.y + h[1] * wa.w + h[2] * wb.y + h[3] * wb.w;
#pragma unroll
    for (int o = 16; o > 0; o >>= 1) {
        d0 += __shfl_xor_sync(0xffffffffu, d0, o);
        d1 += __shfl_xor_sync(0xffffffffu, d1, o);
    }
    if (lane == 0) {
        g_y2[2 * w]     = dw * d0;
        g_y2[2 * w + 1] = dw * d1;
    }
}

// ---------------- aggregation 2 (2 nodes / warp) + b2 -> out ----------------
__global__ void __launch_bounds__(256) k_agg2(const float* __restrict__ b2,
                                              float* __restrict__ out) {
    int warpId = (blockIdx.x * blockDim.x + threadIdx.x) >> 5;
    int lane   = threadIdx.x & 31;
    int l16    = lane & 15;
    int w      = warpId * 2 + (lane >> 4);

    float ax = 0.f, ay = 0.f;
    if (w < N_NODES) {
        const int* __restrict__ bkt = g_bkt + (size_t)w * CAP;
        int cnt = g_cnt[w];
        int c   = cnt < CAP ? cnt : CAP;
        for (int e = l16; e < c; e += 16) {
            int s = bkt[e];
            float2 v = *(const float2*)(g_y2 + 2 * s);
            ax += v.x; ay += v.y;
        }
    }
#pragma unroll
    for (int o = 8; o > 0; o >>= 1) {
        ax += __shfl_xor_sync(0xffffffffu, ax, o);
        ay += __shfl_xor_sync(0xffffffffu, ay, o);
    }
    if (l16 == 0 && w < N_NODES) {
        float dv = g_dinv[w];
        out[2 * w]     = dv * (ax + g_y2[2 * w])     + b2[0];
        out[2 * w + 1] = dv * (ay + g_y2[2 * w + 1]) + b2[1];
    }
}

// ---------------- launch ----------------
extern "C" void kernel_launch(void* const* d_in, const int* in_sizes, int n_in,
                              void* d_out, int out_size) {
    const float* x     = (const float*)d_in[0];
    const int*   ei    = (const int*)d_in[1];     // int32 (JAX w/o x64)
    const float* bn0_g = (const float*)d_in[2];
    const float* bn0_b = (const float*)d_in[3];
    const float* bn0_m = (const float*)d_in[4];
    const float* bn0_v = (const float*)d_in[5];
    const float* W1    = (const float*)d_in[6];
    const float* b1    = (const float*)d_in[7];
    const float* bn1_g = (const float*)d_in[8];
    const float* bn1_b = (const float*)d_in[9];
    const float* bn1_m = (const float*)d_in[10];
    const float* bn1_v = (const float*)d_in[11];
    const float* W2    = (const float*)d_in[12];
    const float* b2    = (const float*)d_in[13];
    float* out = (float*)d_out;

    const int TB = 256;

    cudaStream_t s2;
    cudaStreamCreateWithFlags(&s2, cudaStreamNonBlocking);
    cudaEvent_t ev1, ev2;
    cudaEventCreateWithFlags(&ev1, cudaEventDisableTiming);
    cudaEventCreateWithFlags(&ev2, cudaEventDisableTiming);

    // fork: gemm1 depends on nothing
    cudaEventRecord(ev1, 0);
    cudaStreamWaitEvent(s2, ev1, 0);
    k_gemm1<<<(N_NODES + 127) / 128, TB, 0, s2>>>(x, bn0_g, bn0_b, bn0_m, bn0_v, W1);
    cudaEventRecord(ev2, s2);

    void* cntp = nullptr;
    cudaGetSymbolAddress(&cntp, g_cnt);
    cudaMemsetAsync(cntp, 0, sizeof(int) * N_NODES, 0);

    k_fill<<<(N_EDGES / 2 + TB - 1) / TB, TB>>>(ei);

    // join: prescale + dinv + bucket pad (needs gemm1 + fill), then aggregate
    cudaStreamWaitEvent(0, ev2, 0);
    k_scale<<<((N_NODES + 1) * 32 + TB - 1) / TB, TB>>>();
    k_agg1<<<(N_NODES * 32 + TB - 1) / TB, TB>>>(bn1_g, bn1_b, bn1_m, bn1_v, b1, W2);
    k_agg2<<<(N_NODES * 16 + TB - 1) / TB, TB>>>(b2, out);
}

// round 14
// speedup vs baseline: 1.3848x; 1.3848x over previous
#include <cuda_runtime.h>
#include <cuda_fp16.h>
#include <cstdint>

#define N_NODES 50000
#define N_EDGES 1600000
#define F_IN    128
#define H_DIM   128
#define BN_EPS  1e-5f
#define CAP     128          // bucket capacity per node (Poisson λ=32: P(deg>128) ~ 1e-40)

// ---------------- scratch (no cudaMalloc allowed) ----------------
// g_cnt starts zero (BSS) and is re-zeroed by k_agg2 at the end of every launch.
__device__ int    g_cnt[N_NODES];                 // in-degree (edges only)
__device__ float  g_dinv[N_NODES];
__device__ int    g_bkt[(size_t)N_NODES * CAP];   // bucketed CSR
// +1 zero row at index N_NODES for padded gather lanes
__device__ __half g_y1[(size_t)(N_NODES + 1) * H_DIM];  // bn0(x)@W1, prescaled by dinv
__device__ float  g_y2[(size_t)N_NODES * 2];            // dinv * (h2 @ W2)

// ---------------- one-pass bucket fill (2 edges / thread, proven) ----------------
__global__ void k_fill(const int* __restrict__ ei) {
    int t = blockIdx.x * blockDim.x + threadIdx.x;
    int e = t * 2;
    if (e < N_EDGES) {
        int2 sv = *(const int2*)(ei + e);
        int2 dv = *(const int2*)(ei + N_EDGES + e);
        int p0 = atomicAdd(&g_cnt[dv.x], 1);
        if (p0 < CAP) g_bkt[(size_t)dv.x * CAP + p0] = sv.x;
        int p1 = atomicAdd(&g_cnt[dv.y], 1);
        if (p1 < CAP) g_bkt[(size_t)dv.y * CAP + p1] = sv.y;
    }
}

// ---------------- prescale y1 by dinv, persist dinv, zero pad row ----------------
__global__ void __launch_bounds__(256) k_scale() {
    int t = blockIdx.x * blockDim.x + threadIdx.x;   // one uint2 (4 halves) each
    if (t >= (N_NODES + 1) * 32) return;
    int row = t >> 5;
    uint2* Y = (uint2*)g_y1;
    if (row < N_NODES) {
        float d = rsqrtf((float)(g_cnt[row] + 1));   // +1 self loop
        if ((t & 31) == 0) g_dinv[row] = d;
        uint2 u = Y[t];
        __half2 dv2 = __float2half2_rn(d);
        *(__half2*)&u.x = __hmul2(*(__half2*)&u.x, dv2);
        *(__half2*)&u.y = __hmul2(*(__half2*)&u.y, dv2);
        Y[t] = u;
    } else {
        Y[t] = make_uint2(0u, 0u);
    }
}

// ============== GEMM1: y1 = bn0(x) @ W1  (HMMA fp16, fp32 accum) ==============
__device__ __forceinline__ uint32_t smem_u32(const void* p) {
    return (uint32_t)__cvta_generic_to_shared(p);
}
__device__ __forceinline__ void ldm_x4(uint32_t& r0, uint32_t& r1, uint32_t& r2, uint32_t& r3,
                                       uint32_t a) {
    asm volatile("ldmatrix.sync.aligned.m8n8.x4.shared.b16 {%0,%1,%2,%3}, [%4];"
                 : "=r"(r0), "=r"(r1), "=r"(r2), "=r"(r3) : "r"(a));
}
__device__ __forceinline__ void ldm_x4_t(uint32_t& r0, uint32_t& r1, uint32_t& r2, uint32_t& r3,
                                         uint32_t a) {
    asm volatile("ldmatrix.sync.aligned.m8n8.x4.trans.shared.b16 {%0,%1,%2,%3}, [%4];"
                 : "=r"(r0), "=r"(r1), "=r"(r2), "=r"(r3) : "r"(a));
}
__device__ __forceinline__ void mma16816(float* c, uint32_t a0, uint32_t a1, uint32_t a2,
                                         uint32_t a3, uint32_t b0, uint32_t b1) {
    asm volatile("mma.sync.aligned.m16n8k16.row.col.f32.f16.f16.f32 "
                 "{%0,%1,%2,%3}, {%4,%5,%6,%7}, {%8,%9}, {%0,%1,%2,%3};"
                 : "+f"(c[0]), "+f"(c[1]), "+f"(c[2]), "+f"(c[3])
                 : "r"(a0), "r"(a1), "r"(a2), "r"(a3), "r"(b0), "r"(b1));
}

#define SW_STRIDE 136
#define SA_STRIDE 24

__global__ void __launch_bounds__(256) k_gemm1(
        const float* __restrict__ x,
        const float* __restrict__ g0, const float* __restrict__ b0,
        const float* __restrict__ m0, const float* __restrict__ v0,
        const float* __restrict__ W1) {
    __shared__ __half sW[128 * SW_STRIDE];
    __shared__ __half sA[128 * SA_STRIDE];
    __shared__ float  sa[128], sc[128];

    const int tid  = threadIdx.x;
    const int wid  = tid >> 5;
    const int lane = tid & 31;
    const int bm   = blockIdx.x * 128;

    if (tid < 128) {
        float a = g0[tid] * rsqrtf(v0[tid] + BN_EPS);
        sa[tid] = a;
        sc[tid] = b0[tid] - m0[tid] * a;
    }
    for (int i = tid; i < 128 * 128; i += 256) {
        int k = i >> 7, n = i & 127;
        sW[k * SW_STRIDE + n] = __float2half(W1[i]);
    }
    __syncthreads();

    const int m0r   = wid * 16;
    const uint32_t aAddr = smem_u32(&sA[(m0r + (lane & 15)) * SA_STRIDE + (lane >> 4) * 8]);
    const int bRow  = (lane & 7) + ((lane >> 4) & 1) * 8;
    const int bColO = ((lane >> 3) & 1) * 8;

    const int arow = tid >> 1;
    const int akk  = (tid & 1) * 8;
    const int grow = bm + arow;

    float acc[16][4];
#pragma unroll
    for (int t = 0; t < 16; t++)
#pragma unroll
        for (int j = 0; j < 4; j++) acc[t][j] = 0.f;

    for (int k0 = 0; k0 < F_IN; k0 += 16) {
        float4 xv0 = make_float4(0.f, 0.f, 0.f, 0.f), xv1 = xv0;
        if (grow < N_NODES) {
            xv0 = *(const float4*)(x + (size_t)grow * F_IN + k0 + akk);
            xv1 = *(const float4*)(x + (size_t)grow * F_IN + k0 + akk + 4);
        }
        __half* dst = &sA[arow * SA_STRIDE + akk];
        dst[0] = __float2half(xv0.x * sa[k0 + akk]     + sc[k0 + akk]);
        dst[1] = __float2half(xv0.y * sa[k0 + akk + 1] + sc[k0 + akk + 1]);
        dst[2] = __float2half(xv0.z * sa[k0 + akk + 2] + sc[k0 + akk + 2]);
        dst[3] = __float2half(xv0.w * sa[k0 + akk + 3] + sc[k0 + akk + 3]);
        dst[4] = __float2half(xv1.x * sa[k0 + akk + 4] + sc[k0 + akk + 4]);
        dst[5] = __float2half(xv1.y * sa[k0 + akk + 5] + sc[k0 + akk + 5]);
        dst[6] = __float2half(xv1.z * sa[k0 + akk + 6] + sc[k0 + akk + 6]);
        dst[7] = __float2half(xv1.w * sa[k0 + akk + 7] + sc[k0 + akk + 7]);
        __syncthreads();

        uint32_t a0, a1, a2, a3;
        ldm_x4(a0, a1, a2, a3, aAddr);
#pragma unroll
        for (int np = 0; np < 8; np++) {
            uint32_t r0, r1, r2, r3;
            uint32_t bAddr = smem_u32(&sW[(k0 + bRow) * SW_STRIDE + np * 16 + bColO]);
            ldm_x4_t(r0, r1, r2, r3, bAddr);
            mma16816(acc[np * 2],     a0, a1, a2, a3, r0, r2);
            mma16816(acc[np * 2 + 1], a0, a1, a2, a3, r1, r3);
        }
        __syncthreads();
    }

    int r0g = bm + m0r + (lane >> 2);
    int r1g = r0g + 8;
    int ncol = (lane & 3) * 2;
#pragma unroll
    for (int t = 0; t < 16; t++) {
        int n = t * 8 + ncol;
        if (r0g < N_NODES) {
            __half2 h = __floats2half2_rn(acc[t][0], acc[t][1]);
            *(__half2*)(g_y1 + (size_t)r0g * H_DIM + n) = h;
        }
        if (r1g < N_NODES) {
            __half2 h = __floats2half2_rn(acc[t][2], acc[t][3]);
            *(__half2*)(g_y1 + (size_t)r1g * H_DIM + n) = h;
        }
    }
}

// ========= agg1 + bn1 + relu + GEMM2 fused (warp per node) — R11 proven body =========
__global__ void __launch_bounds__(256) k_agg1(
        const float* __restrict__ g1, const float* __restrict__ be1,
        const float* __restrict__ m1, const float* __restrict__ v1,
        const float* __restrict__ b1, const float* __restrict__ W2) {
    int w = (blockIdx.x * blockDim.x + threadIdx.x) >> 5;
    int lane = threadIdx.x & 31;
    if (w >= N_NODES) return;

    const uint2* __restrict__ Y = (const uint2*)g_y1;   // 32 uint2 per row (prescaled)
    const int* __restrict__ bkt = g_bkt + (size_t)w * CAP;
    int cnt  = g_cnt[w];
    if (cnt > CAP) cnt = CAP;
    float dw = g_dinv[w];

    // self loop: prescaled own row, fp32
    float2 acc0, acc1;
    {
        uint2 u = Y[(size_t)w * 32 + lane];
        acc0 = __half22float2(*(__half2*)&u.x);
        acc1 = __half22float2(*(__half2*)&u.y);
    }

    for (int j0 = 0; j0 < cnt; j0 += 32) {
        int sl = (j0 + lane < cnt) ? bkt[j0 + lane] : N_NODES;  // pad -> zero row
        int m = cnt - j0; if (m > 32) m = 32;
        int ng = (m + 7) >> 3;
        for (int g = 0; g < ng; g++) {
            __half2 a0 = __float2half2_rn(0.f);
            __half2 a1 = __float2half2_rn(0.f);
#pragma unroll
            for (int j = 0; j < 8; j++) {
                int s = __shfl_sync(0xffffffffu, sl, g * 8 + j);
                uint2 u = Y[(size_t)s * 32 + lane];
                a0 = __hadd2(a0, *(__half2*)&u.x);
                a1 = __hadd2(a1, *(__half2*)&u.y);
            }
            float2 f0 = __half22float2(a0);
            float2 f1 = __half22float2(a1);
            acc0.x += f0.x; acc0.y += f0.y;
            acc1.x += f1.x; acc1.y += f1.y;
        }
    }

    // bn1 + relu
    int f = lane * 4;
    float4 ga = *(const float4*)(g1 + f);
    float4 va = *(const float4*)(v1 + f);
    float4 ba = *(const float4*)(be1 + f);
    float4 ma = *(const float4*)(m1 + f);
    float4 bb = *(const float4*)(b1 + f);

    float h[4];
    {
        float a = ga.x * rsqrtf(va.x + BN_EPS);
        h[0] = fmaxf(a * (dw * acc0.x + bb.x) + (ba.x - ma.x * a), 0.f);
        a = ga.y * rsqrtf(va.y + BN_EPS);
        h[1] = fmaxf(a * (dw * acc0.y + bb.y) + (ba.y - ma.y * a), 0.f);
        a = ga.z * rsqrtf(va.z + BN_EPS);
        h[2] = fmaxf(a * (dw * acc1.x + bb.z) + (ba.z - ma.z * a), 0.f);
        a = ga.w * rsqrtf(va.w + BN_EPS);
        h[3] = fmaxf(a * (dw * acc1.y + bb.w) + (ba.w - ma.w * a), 0.f);
    }

    // fused GEMM2: y2[w] = dinv[w] * (h2[w] @ W2)
    float4 wa = *(const float4*)(W2 + f * 2);
    float4 wb = *(const float4*)(W2 + f * 2 + 4);
    float d0 = h[0] * wa.x + h[1] * wa.z + h[2] * wb.x + h[3] * wb.z;
    float d1 = h[0] * wa.y + h[1] * wa.w + h[2] * wb.y + h[3] * wb.w;
#pragma unroll
    for (int o = 16; o > 0; o >>= 1) {
        d0 += __shfl_xor_sync(0xffffffffu, d0, o);
        d1 += __shfl_xor_sync(0xffffffffu, d1, o);
    }
    if (lane == 0) {
        g_y2[2 * w]     = dw * d0;
        g_y2[2 * w + 1] = dw * d1;
    }
}

// ------- aggregation 2 (2 nodes / warp) + b2 -> out; self-cleans g_cnt -------
__global__ void __launch_bounds__(256) k_agg2(const float* __restrict__ b2,
                                              float* __restrict__ out) {
    int warpId = (blockIdx.x * blockDim.x + threadIdx.x) >> 5;
    int lane   = threadIdx.x & 31;
    int l16    = lane & 15;
    int w      = warpId * 2 + (lane >> 4);

    float ax = 0.f, ay = 0.f;
    if (w < N_NODES) {
        const int* __restrict__ bkt = g_bkt + (size_t)w * CAP;
        int cnt = g_cnt[w];
        if (cnt > CAP) cnt = CAP;
        for (int e = l16; e < cnt; e += 16) {
            int s = bkt[e];
            float2 v = *(const float2*)(g_y2 + 2 * s);
            ax += v.x; ay += v.y;
        }
    }
#pragma unroll
    for (int o = 8; o > 0; o >>= 1) {
        ax += __shfl_xor_sync(0xffffffffu, ax, o);
        ay += __shfl_xor_sync(0xffffffffu, ay, o);
    }
    if (l16 == 0 && w < N_NODES) {
        float dv = g_dinv[w];
        out[2 * w]     = dv * (ax + g_y2[2 * w])     + b2[0];
        out[2 * w + 1] = dv * (ay + g_y2[2 * w + 1]) + b2[1];
        g_cnt[w] = 0;   // restore zero state for the next launch (replaces memset)
    }
}

// ---------------- launch ----------------
extern "C" void kernel_launch(void* const* d_in, const int* in_sizes, int n_in,
                              void* d_out, int out_size) {
    const float* x     = (const float*)d_in[0];
    const int*   ei    = (const int*)d_in[1];     // int32 (JAX w/o x64)
    const float* bn0_g = (const float*)d_in[2];
    const float* bn0_b = (const float*)d_in[3];
    const float* bn0_m = (const float*)d_in[4];
    const float* bn0_v = (const float*)d_in[5];
    const float* W1    = (const float*)d_in[6];
    const float* b1    = (const float*)d_in[7];
    const float* bn1_g = (const float*)d_in[8];
    const float* bn1_b = (const float*)d_in[9];
    const float* bn1_m = (const float*)d_in[10];
    const float* bn1_v = (const float*)d_in[11];
    const float* W2    = (const float*)d_in[12];
    const float* b2    = (const float*)d_in[13];
    float* out = (float*)d_out;

    const int TB = 256;

    cudaStream_t s2;
    cudaStreamCreateWithFlags(&s2, cudaStreamNonBlocking);
    cudaEvent_t ev1, ev2;
    cudaEventCreateWithFlags(&ev1, cudaEventDisableTiming);
    cudaEventCreateWithFlags(&ev2, cudaEventDisableTiming);

    // fork: gemm1 depends on nothing
    cudaEventRecord(ev1, 0);
    cudaStreamWaitEvent(s2, ev1, 0);
    k_gemm1<<<(N_NODES + 127) / 128, TB, 0, s2>>>(x, bn0_g, bn0_b, bn0_m, bn0_v, W1);
    cudaEventRecord(ev2, s2);

    // g_cnt is already zero (initial BSS state / zeroed by previous launch's k_agg2)
    k_fill<<<(N_EDGES / 2 + TB - 1) / TB, TB>>>(ei);

    // join: prescale y1 + compute dinv (needs gemm1 + fill), then aggregate
    cudaStreamWaitEvent(0, ev2, 0);
    k_scale<<<((N_NODES + 1) * 32 + TB - 1) / TB, TB>>>();
    k_agg1<<<(N_NODES * 32 + TB - 1) / TB, TB>>>(bn1_g, bn1_b, bn1_m, bn1_v, b1, W2);
    k_agg2<<<(N_NODES * 16 + TB - 1) / TB, TB>>>(b2, out);
}

// round 15
// speedup vs baseline: 1.4286x; 1.0316x over previous
#include <cuda_runtime.h>
#include <cuda_fp16.h>
#include <cstdint>

#define N_NODES 50000
#define N_EDGES 1600000
#define F_IN    128
#define H_DIM   128
#define BN_EPS  1e-5f
#define CAP     128          // bucket capacity per node (Poisson λ=32: P(deg>128) ~ 1e-40)

// ---------------- scratch (no cudaMalloc allowed) ----------------
// g_cnt starts zero (BSS) and is re-zeroed by k_agg2 at the end of every launch.
__device__ int    g_cnt[N_NODES];                 // in-degree (edges only)
__device__ float  g_dinv[N_NODES];
__device__ int    g_bkt[(size_t)N_NODES * CAP];   // bucketed CSR
// +1 zero row at index N_NODES for padded gather lanes
__device__ __half g_y1[(size_t)(N_NODES + 1) * H_DIM];  // bn0(x)@W1, prescaled by dinv
__device__ float  g_y2[(size_t)N_NODES * 2];            // dinv * (h2 @ W2)

// ---------------- one-pass bucket fill (2 edges / thread, proven) ----------------
__global__ void k_fill(const int* __restrict__ ei) {
    int t = blockIdx.x * blockDim.x + threadIdx.x;
    int e = t * 2;
    if (e < N_EDGES) {
        int2 sv = *(const int2*)(ei + e);
        int2 dv = *(const int2*)(ei + N_EDGES + e);
        int p0 = atomicAdd(&g_cnt[dv.x], 1);
        if (p0 < CAP) g_bkt[(size_t)dv.x * CAP + p0] = sv.x;
        int p1 = atomicAdd(&g_cnt[dv.y], 1);
        if (p1 < CAP) g_bkt[(size_t)dv.y * CAP + p1] = sv.y;
    }
}

// ---------------- prescale y1 by dinv, persist dinv, zero pad row ----------------
__global__ void __launch_bounds__(256) k_scale() {
    int t = blockIdx.x * blockDim.x + threadIdx.x;   // one uint2 (4 halves) each
    if (t >= (N_NODES + 1) * 32) return;
    int row = t >> 5;
    uint2* Y = (uint2*)g_y1;
    if (row < N_NODES) {
        float d = rsqrtf((float)(g_cnt[row] + 1));   // +1 self loop
        if ((t & 31) == 0) g_dinv[row] = d;
        uint2 u = Y[t];
        __half2 dv2 = __float2half2_rn(d);
        *(__half2*)&u.x = __hmul2(*(__half2*)&u.x, dv2);
        *(__half2*)&u.y = __hmul2(*(__half2*)&u.y, dv2);
        Y[t] = u;
    } else {
        Y[t] = make_uint2(0u, 0u);
    }
}

// ============== GEMM1: y1 = bn0(x) @ W1  (HMMA fp16, fp32 accum) ==============
__device__ __forceinline__ uint32_t smem_u32(const void* p) {
    return (uint32_t)__cvta_generic_to_shared(p);
}
__device__ __forceinline__ void ldm_x4(uint32_t& r0, uint32_t& r1, uint32_t& r2, uint32_t& r3,
                                       uint32_t a) {
    asm volatile("ldmatrix.sync.aligned.m8n8.x4.shared.b16 {%0,%1,%2,%3}, [%4];"
                 : "=r"(r0), "=r"(r1), "=r"(r2), "=r"(r3) : "r"(a));
}
__device__ __forceinline__ void ldm_x4_t(uint32_t& r0, uint32_t& r1, uint32_t& r2, uint32_t& r3,
                                         uint32_t a) {
    asm volatile("ldmatrix.sync.aligned.m8n8.x4.trans.shared.b16 {%0,%1,%2,%3}, [%4];"
                 : "=r"(r0), "=r"(r1), "=r"(r2), "=r"(r3) : "r"(a));
}
__device__ __forceinline__ void mma16816(float* c, uint32_t a0, uint32_t a1, uint32_t a2,
                                         uint32_t a3, uint32_t b0, uint32_t b1) {
    asm volatile("mma.sync.aligned.m16n8k16.row.col.f32.f16.f16.f32 "
                 "{%0,%1,%2,%3}, {%4,%5,%6,%7}, {%8,%9}, {%0,%1,%2,%3};"
                 : "+f"(c[0]), "+f"(c[1]), "+f"(c[2]), "+f"(c[3])
                 : "r"(a0), "r"(a1), "r"(a2), "r"(a3), "r"(b0), "r"(b1));
}

#define SW_STRIDE 136
#define SA_STRIDE 24

__global__ void __launch_bounds__(256) k_gemm1(
        const float* __restrict__ x,
        const float* __restrict__ g0, const float* __restrict__ b0,
        const float* __restrict__ m0, const float* __restrict__ v0,
        const float* __restrict__ W1) {
    __shared__ __half sW[128 * SW_STRIDE];
    __shared__ __half sA[128 * SA_STRIDE];
    __shared__ float  sa[128], sc[128];

    const int tid  = threadIdx.x;
    const int wid  = tid >> 5;
    const int lane = tid & 31;
    const int bm   = blockIdx.x * 128;

    if (tid < 128) {
        float a = g0[tid] * rsqrtf(v0[tid] + BN_EPS);
        sa[tid] = a;
        sc[tid] = b0[tid] - m0[tid] * a;
    }
    for (int i = tid; i < 128 * 128; i += 256) {
        int k = i >> 7, n = i & 127;
        sW[k * SW_STRIDE + n] = __float2half(W1[i]);
    }
    __syncthreads();

    const int m0r   = wid * 16;
    const uint32_t aAddr = smem_u32(&sA[(m0r + (lane & 15)) * SA_STRIDE + (lane >> 4) * 8]);
    const int bRow  = (lane & 7) + ((lane >> 4) & 1) * 8;
    const int bColO = ((lane >> 3) & 1) * 8;

    const int arow = tid >> 1;
    const int akk  = (tid & 1) * 8;
    const int grow = bm + arow;

    float acc[16][4];
#pragma unroll
    for (int t = 0; t < 16; t++)
#pragma unroll
        for (int j = 0; j < 4; j++) acc[t][j] = 0.f;

    for (int k0 = 0; k0 < F_IN; k0 += 16) {
        float4 xv0 = make_float4(0.f, 0.f, 0.f, 0.f), xv1 = xv0;
        if (grow < N_NODES) {
            xv0 = *(const float4*)(x + (size_t)grow * F_IN + k0 + akk);
            xv1 = *(const float4*)(x + (size_t)grow * F_IN + k0 + akk + 4);
        }
        __half* dst = &sA[arow * SA_STRIDE + akk];
        dst[0] = __float2half(xv0.x * sa[k0 + akk]     + sc[k0 + akk]);
        dst[1] = __float2half(xv0.y * sa[k0 + akk + 1] + sc[k0 + akk + 1]);
        dst[2] = __float2half(xv0.z * sa[k0 + akk + 2] + sc[k0 + akk + 2]);
        dst[3] = __float2half(xv0.w * sa[k0 + akk + 3] + sc[k0 + akk + 3]);
        dst[4] = __float2half(xv1.x * sa[k0 + akk + 4] + sc[k0 + akk + 4]);
        dst[5] = __float2half(xv1.y * sa[k0 + akk + 5] + sc[k0 + akk + 5]);
        dst[6] = __float2half(xv1.z * sa[k0 + akk + 6] + sc[k0 + akk + 6]);
        dst[7] = __float2half(xv1.w * sa[k0 + akk + 7] + sc[k0 + akk + 7]);
        __syncthreads();

        uint32_t a0, a1, a2, a3;
        ldm_x4(a0, a1, a2, a3, aAddr);
#pragma unroll
        for (int np = 0; np < 8; np++) {
            uint32_t r0, r1, r2, r3;
            uint32_t bAddr = smem_u32(&sW[(k0 + bRow) * SW_STRIDE + np * 16 + bColO]);
            ldm_x4_t(r0, r1, r2, r3, bAddr);
            mma16816(acc[np * 2],     a0, a1, a2, a3, r0, r2);
            mma16816(acc[np * 2 + 1], a0, a1, a2, a3, r1, r3);
        }
        __syncthreads();
    }

    int r0g = bm + m0r + (lane >> 2);
    int r1g = r0g + 8;
    int ncol = (lane & 3) * 2;
#pragma unroll
    for (int t = 0; t < 16; t++) {
        int n = t * 8 + ncol;
        if (r0g < N_NODES) {
            __half2 h = __floats2half2_rn(acc[t][0], acc[t][1]);
            *(__half2*)(g_y1 + (size_t)r0g * H_DIM + n) = h;
        }
        if (r1g < N_NODES) {
            __half2 h = __floats2half2_rn(acc[t][2], acc[t][3]);
            *(__half2*)(g_y1 + (size_t)r1g * H_DIM + n) = h;
        }
    }
}

// ========= agg1 + bn1 + relu + GEMM2 fused (warp per node) =========
// Full 32-edge chunks: fully unrolled, literal shuffle lanes, unconditional loads.
// Tail chunk: dynamic path padded with the zero row.
__global__ void __launch_bounds__(256) k_agg1(
        const float* __restrict__ g1, const float* __restrict__ be1,
        const float* __restrict__ m1, const float* __restrict__ v1,
        const float* __restrict__ b1, const float* __restrict__ W2) {
    int w = (blockIdx.x * blockDim.x + threadIdx.x) >> 5;
    int lane = threadIdx.x & 31;
    if (w >= N_NODES) return;

    const uint2* __restrict__ Y = (const uint2*)g_y1;   // 32 uint2 per row (prescaled)
    const int* __restrict__ bp = g_bkt + (size_t)w * CAP;
    int cnt  = g_cnt[w];
    if (cnt > CAP) cnt = CAP;
    float dw = g_dinv[w];

    // self loop: prescaled own row, fp32
    float2 acc0, acc1;
    {
        uint2 u = Y[(size_t)w * 32 + lane];
        acc0 = __half22float2(*(__half2*)&u.x);
        acc1 = __half22float2(*(__half2*)&u.y);
    }

    const int nfull = cnt >> 5;
    for (int c = 0; c < nfull; c++) {
        int sl = bp[lane];          // unconditional: full chunk
        bp += 32;
#pragma unroll
        for (int g = 0; g < 4; g++) {
            __half2 a0 = __float2half2_rn(0.f);
            __half2 a1 = __float2half2_rn(0.f);
#pragma unroll
            for (int j = 0; j < 8; j++) {
                int s = __shfl_sync(0xffffffffu, sl, g * 8 + j);   // literal lane
                uint2 u = Y[(size_t)s * 32 + lane];
                a0 = __hadd2(a0, *(__half2*)&u.x);
                a1 = __hadd2(a1, *(__half2*)&u.y);
            }
            float2 f0 = __half22float2(a0);
            float2 f1 = __half22float2(a1);
            acc0.x += f0.x; acc0.y += f0.y;
            acc1.x += f1.x; acc1.y += f1.y;
        }
    }

    int rem = cnt & 31;
    if (rem) {
        int sl = (lane < rem) ? bp[lane] : N_NODES;   // pad -> zero row
        int ng = (rem + 7) >> 3;
        for (int g = 0; g < ng; g++) {
            __half2 a0 = __float2half2_rn(0.f);
            __half2 a1 = __float2half2_rn(0.f);
#pragma unroll
            for (int j = 0; j < 8; j++) {
                int s = __shfl_sync(0xffffffffu, sl, g * 8 + j);
                uint2 u = Y[(size_t)s * 32 + lane];
                a0 = __hadd2(a0, *(__half2*)&u.x);
                a1 = __hadd2(a1, *(__half2*)&u.y);
            }
            float2 f0 = __half22float2(a0);
            float2 f1 = __half22float2(a1);
            acc0.x += f0.x; acc0.y += f0.y;
            acc1.x += f1.x; acc1.y += f1.y;
        }
    }

    // bn1 + relu
    int f = lane * 4;
    float4 ga = *(const float4*)(g1 + f);
    float4 va = *(const float4*)(v1 + f);
    float4 ba = *(const float4*)(be1 + f);
    float4 ma = *(const float4*)(m1 + f);
    float4 bb = *(const float4*)(b1 + f);

    float h[4];
    {
        float a = ga.x * rsqrtf(va.x + BN_EPS);
        h[0] = fmaxf(a * (dw * acc0.x + bb.x) + (ba.x - ma.x * a), 0.f);
        a = ga.y * rsqrtf(va.y + BN_EPS);
        h[1] = fmaxf(a * (dw * acc0.y + bb.y) + (ba.y - ma.y * a), 0.f);
        a = ga.z * rsqrtf(va.z + BN_EPS);
        h[2] = fmaxf(a * (dw * acc1.x + bb.z) + (ba.z - ma.z * a), 0.f);
        a = ga.w * rsqrtf(va.w + BN_EPS);
        h[3] = fmaxf(a * (dw * acc1.y + bb.w) + (ba.w - ma.w * a), 0.f);
    }

    // fused GEMM2: y2[w] = dinv[w] * (h2[w] @ W2)
    float4 wa = *(const float4*)(W2 + f * 2);
    float4 wb = *(const float4*)(W2 + f * 2 + 4);
    float d0 = h[0] * wa.x + h[1] * wa.z + h[2] * wb.x + h[3] * wb.z;
    float d1 = h[0] * wa.y + h[1] * wa.w + h[2] * wb.y + h[3] * wb.w;
#pragma unroll
    for (int o = 16; o > 0; o >>= 1) {
        d0 += __shfl_xor_sync(0xffffffffu, d0, o);
        d1 += __shfl_xor_sync(0xffffffffu, d1, o);
    }
    if (lane == 0) {
        g_y2[2 * w]     = dw * d0;
        g_y2[2 * w + 1] = dw * d1;
    }
}

// ------- aggregation 2 (2 nodes / warp) + b2 -> out; self-cleans g_cnt -------
__global__ void __launch_bounds__(256) k_agg2(const float* __restrict__ b2,
                                              float* __restrict__ out) {
    int warpId = (blockIdx.x * blockDim.x + threadIdx.x) >> 5;
    int lane   = threadIdx.x & 31;
    int l16    = lane & 15;
    int w      = warpId * 2 + (lane >> 4);

    float ax = 0.f, ay = 0.f;
    if (w < N_NODES) {
        const int* __restrict__ bkt = g_bkt + (size_t)w * CAP;
        int cnt = g_cnt[w];
        if (cnt > CAP) cnt = CAP;
        for (int e = l16; e < cnt; e += 16) {
            int s = bkt[e];
            float2 v = *(const float2*)(g_y2 + 2 * s);
            ax += v.x; ay += v.y;
        }
    }
#pragma unroll
    for (int o = 8; o > 0; o >>= 1) {
        ax += __shfl_xor_sync(0xffffffffu, ax, o);
        ay += __shfl_xor_sync(0xffffffffu, ay, o);
    }
    if (l16 == 0 && w < N_NODES) {
        float dv = g_dinv[w];
        out[2 * w]     = dv * (ax + g_y2[2 * w])     + b2[0];
        out[2 * w + 1] = dv * (ay + g_y2[2 * w + 1]) + b2[1];
        g_cnt[w] = 0;   // restore zero state for the next launch (replaces memset)
    }
}

// ---------------- launch ----------------
extern "C" void kernel_launch(void* const* d_in, const int* in_sizes, int n_in,
                              void* d_out, int out_size) {
    const float* x     = (const float*)d_in[0];
    const int*   ei    = (const int*)d_in[1];     // int32 (JAX w/o x64)
    const float* bn0_g = (const float*)d_in[2];
    const float* bn0_b = (const float*)d_in[3];
    const float* bn0_m = (const float*)d_in[4];
    const float* bn0_v = (const float*)d_in[5];
    const float* W1    = (const float*)d_in[6];
    const float* b1    = (const float*)d_in[7];
    const float* bn1_g = (const float*)d_in[8];
    const float* bn1_b = (const float*)d_in[9];
    const float* bn1_m = (const float*)d_in[10];
    const float* bn1_v = (const float*)d_in[11];
    const float* W2    = (const float*)d_in[12];
    const float* b2    = (const float*)d_in[13];
    float* out = (float*)d_out;

    const int TB = 256;

    cudaStream_t s2;
    cudaStreamCreateWithFlags(&s2, cudaStreamNonBlocking);
    cudaEvent_t ev1, ev2;
    cudaEventCreateWithFlags(&ev1, cudaEventDisableTiming);
    cudaEventCreateWithFlags(&ev2, cudaEventDisableTiming);

    // fork: gemm1 depends on nothing
    cudaEventRecord(ev1, 0);
    cudaStreamWaitEvent(s2, ev1, 0);
    k_gemm1<<<(N_NODES + 127) / 128, TB, 0, s2>>>(x, bn0_g, bn0_b, bn0_m, bn0_v, W1);
    cudaEventRecord(ev2, s2);

    // g_cnt is already zero (initial BSS state / zeroed by previous launch's k_agg2)
    k_fill<<<(N_EDGES / 2 + TB - 1) / TB, TB>>>(ei);

    // join: prescale y1 + compute dinv (needs gemm1 + fill), then aggregate
    cudaStreamWaitEvent(0, ev2, 0);
    k_scale<<<((N_NODES + 1) * 32 + TB - 1) / TB, TB>>>();
    k_agg1<<<(N_NODES * 32 + TB - 1) / TB, TB>>>(bn1_g, bn1_b, bn1_m, bn1_v, b1, W2);
    k_agg2<<<(N_NODES * 16 + TB - 1) / TB, TB>>>(b2, out);
}